// round 16
// baseline (speedup 1.0000x reference)
#include <cuda_runtime.h>

namespace {
constexpr int B = 2, H = 128, W = 256, MD = 34, LD = 32;
constexpr int NH = 4, SH = 64, K = 25, P = 7, R = 3;
constexpr int FF1 = 512, FF2 = 256;
constexpr int PP = P * P; // 49
constexpr long M_PIX = (long)B * H * W; // 65536

// ---------------- disco config (R15, measured best) ----------------
constexpr int TW   = 32;
constexpr int PIX  = 8;
constexpr int NGRP = TW / PIX;
constexpr int TAD  = 256;
constexpr int XCOLS = TW + 2 * R; // 38

constexpr int WEFFB4_N = 8 * 4 * 32;        // 1024 float4 per latitude
constexpr int HW1B4_N  = 4 * 4 * 4 * 32;    // 2048 float4
constexpr int FW1B_F  = 64 * 5 * 32 * 2;     // 20480
constexpr int FW2B_F  = 16 * 32 * 4 * 32 * 2;// 131072
constexpr int FW3B_F  = 4 * 32 * 32 * 2;     // 8192

constexpr int OFF_SX   = 0;
constexpr int OFF_SXC  = OFF_SX + LD * P * XCOLS;
constexpr int OFF_SDB  = OFF_SXC + LD * TW;
constexpr int OFF_HB1  = OFF_SDB + SH;
constexpr int OFF_HW2  = OFF_HB1 + NH * 32;
constexpr int OFF_HB2  = OFF_HW2 + NH * 32;
constexpr int SMEM_D_F = OFF_HB2 + NH;     // 39.4 KB

__device__ __forceinline__ float gelu_exact(float v) {
    return 0.5f * v * (1.0f + erff(v * 0.70710678118654752440f));
}

__device__ __forceinline__ float f2tf_f(float f) {
    unsigned u;
    asm("cvt.rna.tf32.f32 %0, %1;" : "=r"(u) : "f"(f));
    return __uint_as_float(u);
}

__device__ __forceinline__ void mma_tf32(float c[4], const float4& a, const float2& b) {
    const unsigned* A = reinterpret_cast<const unsigned*>(&a);
    const unsigned* Bv = reinterpret_cast<const unsigned*>(&b);
    asm volatile(
        "mma.sync.aligned.m16n8k8.row.col.f32.tf32.tf32.f32 "
        "{%0,%1,%2,%3},{%4,%5,%6,%7},{%8,%9},{%0,%1,%2,%3};\n"
        : "+f"(c[0]), "+f"(c[1]), "+f"(c[2]), "+f"(c[3])
        : "r"(A[0]), "r"(A[1]), "r"(A[2]), "r"(A[3]), "r"(Bv[0]), "r"(Bv[1]));
}
} // namespace

// device-global scratch (no runtime allocation)
__device__ __align__(16) float4 g_weffB4[H * WEFFB4_N];
__device__ __align__(16) float4 g_hw1B4[HW1B4_N];
__device__ __align__(16) float g_fw1B[FW1B_F];
__device__ __align__(16) float g_fw2B[FW2B_F];
__device__ __align__(16) float g_fw3B[FW3B_F];

// =====================================================================
// prep: fold psi into disco_w per latitude -> paired-k8 B-frags
// =====================================================================
__global__ void prep_weffB4(const float* __restrict__ dw,
                            const float* __restrict__ psi) {
    const int h = blockIdx.x;
    for (int e = threadIdx.x; e < WEFFB4_N; e += blockDim.x) {
        int lane = e & 31; int t = e >> 5;
        int kp = t & 3, nt = t >> 2;
        int g = lane >> 2, tg = lane & 3;
        int s = nt * 8 + g;
        int pj[4] = { 16 * kp + tg, 16 * kp + tg + 4,
                      16 * kp + 8 + tg, 16 * kp + 12 + tg };
        float v[4];
        #pragma unroll
        for (int j = 0; j < 4; j++) {
            float acc = 0.f;
            if (pj[j] < PP) {
                #pragma unroll
                for (int k = 0; k < K; k++)
                    acc += dw[s * K + k] * psi[(k * H + h) * PP + pj[j]];
            }
            v[j] = f2tf_f(acc);
        }
        g_weffB4[h * WEFFB4_N + e] = make_float4(v[0], v[1], v[2], v[3]);
    }
}

// =====================================================================
// prep: hw1 / fw1 / fw3 / fw2 — all in ONE kernel (range dispatch)
// =====================================================================
__global__ void prep_weights(const float* __restrict__ hw1,
                             const float* __restrict__ fw1,
                             const float* __restrict__ fw3,
                             const float* __restrict__ fw2) {
    int e = blockIdx.x * blockDim.x + threadIdx.x;
    if (e < HW1B4_N) {
        int lane = e & 31; int t = e >> 5;
        int kp = t & 3; t >>= 2;
        int nt2 = t & 3; int n = t >> 2;
        int g = lane >> 2, tg = lane & 3;
        int o = nt2 * 8 + g;
        int s0 = 16 * kp + tg;
        g_hw1B4[e] = make_float4(
            f2tf_f(hw1[(n * SH + s0)      * 32 + o]),
            f2tf_f(hw1[(n * SH + s0 + 4)  * 32 + o]),
            f2tf_f(hw1[(n * SH + s0 + 8)  * 32 + o]),
            f2tf_f(hw1[(n * SH + s0 + 12) * 32 + o]));
        return;
    }
    e -= HW1B4_N;
    if (e < FW1B_F) {
        int half = e & 1, t = e >> 1;
        int lane = t & 31; t >>= 5;
        int ks = t % 5, nt = t / 5;
        int g = lane >> 2, tg = lane & 3;
        int k = ks * 8 + tg + 4 * half;
        int n = nt * 8 + g;
        g_fw1B[e] = (k < MD) ? f2tf_f(fw1[k * FF1 + n]) : 0.f;
        return;
    }
    e -= FW1B_F;
    if (e < FW3B_F) {
        int half = e & 1, t = e >> 1;
        int lane = t & 31; t >>= 5;
        int ks = t & 31, nt = t >> 5;
        int g = lane >> 2, tg = lane & 3;
        int k = ks * 8 + tg + 4 * half;
        int n = nt * 8 + g;
        g_fw3B[e] = f2tf_f(fw3[k * LD + n]);
        return;
    }
    e -= FW3B_F;
    if (e < FW2B_F) {
        int kc = e >> 13, r = e & 8191;
        int half = r & 1; r >>= 1;
        int lane = r & 31; r >>= 5;
        int ks = r & 3; int nt = r >> 2;
        int g = lane >> 2, tg = lane & 3;
        int k = kc * 32 + ks * 8 + tg + 4 * half;
        int n = nt * 8 + g;
        g_fw2B[e] = f2tf_f(fw2[k * FF2 + n]);
    }
}

// =====================================================================
// disco conv + head MLP + residual — byte-for-byte R15 (measured best)
// =====================================================================
__global__ __launch_bounds__(TAD, 2) void disco_head_mma(
    const float* __restrict__ x,   const float* __restrict__ db,
    const float* __restrict__ hb1, const float* __restrict__ hw2,
    const float* __restrict__ hb2, float* __restrict__ out)
{
    extern __shared__ float sm[];
    float* sx   = sm + OFF_SX;
    float* sxc  = sm + OFF_SXC;
    float* sdb  = sm + OFF_SDB;
    float* shb1 = sm + OFF_HB1;
    float* shw2 = sm + OFF_HW2;
    float* shb2 = sm + OFF_HB2;

    const int tid = threadIdx.x;
    const int lane = tid & 31, mt = tid >> 5;
    const int g  = lane >> 2, tg = lane & 3;
    const int w0 = blockIdx.x * TW;
    const int h  = blockIdx.y;
    const int b  = blockIdx.z;

    if (tid < SH) sdb[tid] = db[tid];
    if (tid < NH * 32) { shb1[tid] = hb1[tid]; shw2[tid] = hw2[tid]; }
    if (tid < NH) shb2[tid] = hb2[tid];

    for (int i = tid; i < LD * P * XCOLS; i += TAD) {
        int ld = i & 31; int pos = i >> 5;
        int r = pos / XCOLS, c = pos % XCOLS;
        int lat = h + r - R; lat = lat < 0 ? 0 : (lat > H - 1 ? H - 1 : lat);
        int lon = (w0 + c - R + W) & (W - 1);
        float v = x[((b * H + lat) * W + lon) * MD + ld];
        sx[(ld * P + r) * XCOLS + c] = f2tf_f(v);
        if (r == R && c >= R && c < R + TW) sxc[ld * TW + (c - R)] = v;
    }
    for (int i = tid; i < TW * 2; i += TAD) {
        int px = i >> 1, j = i & 1;
        int gi = ((b * H + h) * W + (w0 + px)) * MD + LD + j;
        out[gi] = x[gi];
    }
    __syncthreads();

    const int nh  = mt >> 1;
    const int ldA = nh * 8 + 4 * (mt & 1);
    const int px  = g;
    const int base0 = (ldA + 0) * P * XCOLS;
    const int base1 = (ldA + 1) * P * XCOLS;
    const int base2 = (ldA + 2) * P * XCOLS;
    const int base3 = (ldA + 3) * P * XCOLS;

    int roff0[8], roff1[8];
    #pragma unroll
    for (int ks = 0; ks < 8; ks++) {
        int p0 = ks * 8 + tg, p1 = p0 + 4;
        roff0[ks] = (p0 < PP) ? (p0 / 7) * XCOLS + (p0 % 7) : 0;
        roff1[ks] = (p1 < PP) ? (p1 / 7) * XCOLS + (p1 % 7) : 0;
    }

    const float4* swB4 = g_weffB4 + (long)h * WEFFB4_N;
    const float4* h1B4 = g_hw1B4;

    const int src0 = (lane & ~3) | (tg >> 1);
    const int src1 = src0 + 2;
    const bool odd = (tg & 1);

    for (int grp = 0; grp < NGRP; grp++) {
        const int cbase = grp * PIX + px;
        const int cb0 = base0 + cbase, cb1 = base1 + cbase;
        const int cb2 = base2 + cbase, cb3 = base3 + cbase;

        float c1[2][8][4] = {};
        #pragma unroll
        for (int kp = 0; kp < 4; kp++) {
            const int ka = 2 * kp, kb = 2 * kp + 1;
            float4 aA0, aA1, aB0, aB1;
            aA0.x = sx[cb0 + roff0[ka]]; aA0.y = sx[cb1 + roff0[ka]];
            aA0.z = sx[cb0 + roff1[ka]]; aA0.w = sx[cb1 + roff1[ka]];
            aA1.x = sx[cb2 + roff0[ka]]; aA1.y = sx[cb3 + roff0[ka]];
            aA1.z = sx[cb2 + roff1[ka]]; aA1.w = sx[cb3 + roff1[ka]];
            aB0.x = sx[cb0 + roff0[kb]]; aB0.y = sx[cb1 + roff0[kb]];
            aB0.z = sx[cb0 + roff1[kb]]; aB0.w = sx[cb1 + roff1[kb]];
            aB1.x = sx[cb2 + roff0[kb]]; aB1.y = sx[cb3 + roff0[kb]];
            aB1.z = sx[cb2 + roff1[kb]]; aB1.w = sx[cb3 + roff1[kb]];
            #pragma unroll
            for (int nt = 0; nt < 8; nt++) {
                const float4 wb = __ldg(&swB4[(nt * 4 + kp) * 32 + lane]);
                const float2 blo = make_float2(wb.x, wb.y);
                const float2 bhi = make_float2(wb.z, wb.w);
                mma_tf32(c1[0][nt], aA0, blo);
                mma_tf32(c1[1][nt], aA1, blo);
                mma_tf32(c1[0][nt], aB0, bhi);
                mma_tf32(c1[1][nt], aB1, bhi);
            }
        }

        float c2[2][4][4] = {};
        #pragma unroll
        for (int kp = 0; kp < 4; kp++) {
            float4 af[2][2];
            #pragma unroll
            for (int half = 0; half < 2; half++) {
                const int ks = 2 * kp + half;
                const int scol = ks * 8 + 2 * tg;
                const float b0 = sdb[scol], b1 = sdb[scol + 1];
                #pragma unroll
                for (int t = 0; t < 2; t++) {
                    const float y0 = f2tf_f(c1[t][ks][0] + b0);
                    const float y1 = f2tf_f(c1[t][ks][1] + b1);
                    const float y2 = f2tf_f(c1[t][ks][2] + b0);
                    const float y3 = f2tf_f(c1[t][ks][3] + b1);
                    const float u0 = __shfl_sync(0xffffffffu, y0, src0);
                    const float u1 = __shfl_sync(0xffffffffu, y1, src0);
                    const float u2 = __shfl_sync(0xffffffffu, y2, src0);
                    const float u3 = __shfl_sync(0xffffffffu, y3, src0);
                    const float v0 = __shfl_sync(0xffffffffu, y0, src1);
                    const float v1 = __shfl_sync(0xffffffffu, y1, src1);
                    const float v2 = __shfl_sync(0xffffffffu, y2, src1);
                    const float v3 = __shfl_sync(0xffffffffu, y3, src1);
                    af[t][half].x = odd ? u1 : u0;
                    af[t][half].y = odd ? u3 : u2;
                    af[t][half].z = odd ? v1 : v0;
                    af[t][half].w = odd ? v3 : v2;
                }
            }
            #pragma unroll
            for (int nt2 = 0; nt2 < 4; nt2++) {
                const float4 wb = __ldg(&h1B4[((nh * 4 + nt2) * 4 + kp) * 32 + lane]);
                const float2 blo = make_float2(wb.x, wb.y);
                const float2 bhi = make_float2(wb.z, wb.w);
                mma_tf32(c2[0][nt2], af[0][0], blo);
                mma_tf32(c2[1][nt2], af[1][0], blo);
                mma_tf32(c2[0][nt2], af[0][1], bhi);
                mma_tf32(c2[1][nt2], af[1][1], bhi);
            }
        }

        #pragma unroll
        for (int t = 0; t < 2; t++) {
            float part0 = 0.f, part1 = 0.f;
            #pragma unroll
            for (int nt2 = 0; nt2 < 4; nt2++) {
                const int o0 = nt2 * 8 + 2 * tg, o1 = o0 + 1;
                const float w0v = shw2[nh * 32 + o0], w1v = shw2[nh * 32 + o1];
                const float bb0 = shb1[nh * 32 + o0], bb1 = shb1[nh * 32 + o1];
                part0 += gelu_exact(c2[t][nt2][0] + bb0) * w0v
                       + gelu_exact(c2[t][nt2][1] + bb1) * w1v;
                part1 += gelu_exact(c2[t][nt2][2] + bb0) * w0v
                       + gelu_exact(c2[t][nt2][3] + bb1) * w1v;
            }
            part0 += __shfl_xor_sync(0xffffffffu, part0, 1);
            part0 += __shfl_xor_sync(0xffffffffu, part0, 2);
            part1 += __shfl_xor_sync(0xffffffffu, part1, 1);
            part1 += __shfl_xor_sync(0xffffffffu, part1, 2);
            if (tg == 0) {
                const int ld0 = ldA + 2 * t, ld1 = ld0 + 1;
                const int pxg = grp * PIX + px;
                const float v0 = part0 + shb2[nh] + sxc[ld0 * TW + pxg];
                const float v1 = part1 + shb2[nh] + sxc[ld1 * TW + pxg];
                const long o = ((long)(b * H + h) * W + w0 + pxg) * MD;
                out[o + ld0] = v0;
                out[o + ld1] = v1;
            }
        }
    }
}

// =====================================================================
// FFN fully fused, M-tile = 128: warp (mw,nw) owns m-tiles {mw, mw+4}.
// fw2 staged once per 128 rows (halved L2 traffic); stage-3 in two
// 64-row passes reusing one sT2 overlay.
// smem (floats): x-frag stage / buffers [0,24576) + fb1 [24576,25088)
//   mainloop buffers: 2 x (4096 t1c + 8192 fw2) = 24576
//   post: sT2 [0,16384) + sf3 [16384,24576)
// =====================================================================
namespace {
constexpr int F2_BUF = 12288;
constexpr int F2_SF3 = 16384;
constexpr int F2_FB1 = 24576;
constexpr int F2_SMF = 25088;     // floats = 98 KB
}
__global__ __launch_bounds__(512) void ffn_fused(
    const float* __restrict__ xin, const float* __restrict__ fb1,
    const float* __restrict__ fb2, const float* __restrict__ fb3,
    float* __restrict__ out)
{
    extern __shared__ float sm[];
    float* sfb1 = sm + F2_FB1;
    const int tid = threadIdx.x, lane = tid & 31, w = tid >> 5;
    const int mw = w >> 2, nw = w & 3;
    const int g = lane >> 2, tg = lane & 3;
    const long r0 = (long)blockIdx.x * 128;

    sfb1[tid] = fb1[tid];

    // stage x A-frags: 128 rows x 40 k (rounded), then pull to registers
    {
        const int r = tid >> 2;                 // 0..127
        const int rr7 = r & 7, rhi = (r >> 3) & 1, mt = r >> 4;
        const int kb = (tid & 3) * 10;
        #pragma unroll
        for (int j = 0; j < 10; j++) {
            const int k = kb + j;
            const float v = (k < MD) ? f2tf_f(xin[(r0 + r) * MD + k]) : 0.f;
            sm[((mt * 5 + (k >> 3)) * 32 + rr7 * 4 + (k & 3)) * 4
               + rhi + (((k >> 2) & 1) << 1)] = v;
        }
    }
    __syncthreads();
    float4 xfrag[2][5];
    #pragma unroll
    for (int t = 0; t < 2; t++) {
        const int mt = mw + t * 4;
        #pragma unroll
        for (int ks = 0; ks < 5; ks++)
            xfrag[t][ks] = reinterpret_cast<const float4*>(sm)[(mt * 5 + ks) * 32 + lane];
    }
    __syncthreads();

    float c2[2][8][4] = {};
    const float2* fw1b2 = reinterpret_cast<const float2*>(g_fw1B);
    const float4* fw2v4 = reinterpret_cast<const float4*>(g_fw2B);

    for (int kc = 0; kc < 16; kc++) {
        float* buf  = sm + (kc & 1) * F2_BUF;
        float* st1c = buf;
        float* sB   = buf + 4096;

        // fw2 chunk staging (overlaps the t1c compute)
        {
            float4* dst = reinterpret_cast<float4*>(sB);
            #pragma unroll
            for (int i = 0; i < 4; i++)
                dst[tid + i * 512] = fw2v4[kc * 2048 + tid + i * 512];
        }

        // t1 chunk: warp computes m16 x n8 tiles for both its m-tiles;
        // fw1 fragments loaded once, reused across tiles.
        float2 w1[5];
        #pragma unroll
        for (int ks = 0; ks < 5; ks++)
            w1[ks] = __ldg(&fw1b2[(((kc * 4 + nw) * 5) + ks) * 32 + lane]);
        float c1[2][4] = {};
        #pragma unroll
        for (int t = 0; t < 2; t++)
            #pragma unroll
            for (int ks = 0; ks < 5; ks++)
                mma_tf32(c1[t], xfrag[t][ks], w1[ks]);

        {
            const int n = kc * 32 + nw * 8 + 2 * tg;
            const float b0 = sfb1[n], b1 = sfb1[n + 1];
            const int kk0 = 2 * tg, kk1 = kk0 + 1;
            #pragma unroll
            for (int t = 0; t < 2; t++) {
                const int mt = mw + t * 4;
                const int i0 = mt * 512 + (nw * 32 + g * 4 + (kk0 & 3)) * 4 + ((kk0 >> 2) << 1);
                const int i1 = mt * 512 + (nw * 32 + g * 4 + (kk1 & 3)) * 4 + ((kk1 >> 2) << 1);
                *reinterpret_cast<float2*>(st1c + i0) =
                    make_float2(f2tf_f(gelu_exact(c1[t][0] + b0)),
                                f2tf_f(gelu_exact(c1[t][2] + b0)));
                *reinterpret_cast<float2*>(st1c + i1) =
                    make_float2(f2tf_f(gelu_exact(c1[t][1] + b1)),
                                f2tf_f(gelu_exact(c1[t][3] + b1)));
            }
        }
        __syncthreads();

        // stage-2 MMAs: b fragment loaded once, feeds both m-tiles
        #pragma unroll
        for (int ks = 0; ks < 4; ks++) {
            float4 a0 = reinterpret_cast<const float4*>(st1c)[(mw * 4 + ks) * 32 + lane];
            float4 a1 = reinterpret_cast<const float4*>(st1c)[((mw + 4) * 4 + ks) * 32 + lane];
            #pragma unroll
            for (int ni = 0; ni < 8; ni++) {
                float2 bb = reinterpret_cast<const float2*>(sB)[((nw * 8 + ni) * 4 + ks) * 32 + lane];
                mma_tf32(c2[0][ni], a0, bb);
                mma_tf32(c2[1][ni], a1, bb);
            }
        }
    }
    __syncthreads();

    // post: sf3 staged once; two 64-row passes through one sT2 overlay
    float* sT2 = sm;
    float* sf3 = sm + F2_SF3;
    {
        const float4* src = reinterpret_cast<const float4*>(g_fw3B);
        float4* dst = reinterpret_cast<float4*>(sf3);
        #pragma unroll
        for (int i = 0; i < 4; i++) dst[tid + i * 512] = src[tid + i * 512];
    }
    float2* sT2v2 = reinterpret_cast<float2*>(sT2);

    #pragma unroll
    for (int half = 0; half < 2; half++) {
        #pragma unroll
        for (int ni = 0; ni < 8; ni++) {
            const int nt = nw * 8 + ni;
            const int n2 = nt * 8 + 2 * tg;
            const int kk0 = n2 & 7, kk1 = kk0 + 1;
            const int base = (mw * 32 + nt) * 32;
            const int rgA = ((kk0 >> 2) & 1) << 1;
            const int i0 = (base + g * 4 + (kk0 & 3)) * 4 + rgA;
            const int i1 = (base + g * 4 + (kk1 & 3)) * 4 + rgA;
            const float b0 = fb2[n2], b1 = fb2[n2 + 1];
            sT2v2[i0 >> 1] = make_float2(f2tf_f(gelu_exact(c2[half][ni][0] + b0)),
                                         f2tf_f(gelu_exact(c2[half][ni][2] + b0)));
            sT2v2[i1 >> 1] = make_float2(f2tf_f(gelu_exact(c2[half][ni][1] + b1)),
                                         f2tf_f(gelu_exact(c2[half][ni][3] + b1)));
        }
        __syncthreads();

        float c3[4] = {};
        #pragma unroll
        for (int ks = 0; ks < 32; ks++) {
            float4 a = reinterpret_cast<const float4*>(sT2)[(mw * 32 + ks) * 32 + lane];
            float2 bb = reinterpret_cast<const float2*>(sf3)[(nw * 32 + ks) * 32 + lane];
            mma_tf32(c3, a, bb);
        }

        const int col = nw * 8 + 2 * tg;
        const long rlo = r0 + half * 64 + mw * 16 + g, rhi = rlo + 8;
        const float b0 = fb3[col], b1 = fb3[col + 1];
        out[rlo * MD + col]     += c3[0] + b0;
        out[rlo * MD + col + 1] += c3[1] + b1;
        out[rhi * MD + col]     += c3[2] + b0;
        out[rhi * MD + col + 1] += c3[3] + b1;
        __syncthreads();   // sT2 reused by next half
    }
}

extern "C" void kernel_launch(void* const* d_in, const int* in_sizes, int n_in,
                              void* d_out, int out_size) {
    const float* x   = (const float*)d_in[0];
    const float* psi = (const float*)d_in[1];
    const float* dw  = (const float*)d_in[2];
    const float* db  = (const float*)d_in[3];
    const float* hw1 = (const float*)d_in[4];
    const float* hb1 = (const float*)d_in[5];
    const float* hw2 = (const float*)d_in[6];
    const float* hb2 = (const float*)d_in[7];
    const float* fw1 = (const float*)d_in[8];
    const float* fb1 = (const float*)d_in[9];
    const float* fw2 = (const float*)d_in[10];
    const float* fb2 = (const float*)d_in[11];
    const float* fw3 = (const float*)d_in[12];
    const float* fb3 = (const float*)d_in[13];
    float* out = (float*)d_out;

    const size_t smD = SMEM_D_F * sizeof(float);
    const size_t smF = F2_SMF * sizeof(float);
    cudaFuncSetAttribute(disco_head_mma, cudaFuncAttributeMaxDynamicSharedMemorySize, (int)smD);
    cudaFuncSetAttribute(ffn_fused, cudaFuncAttributeMaxDynamicSharedMemorySize, (int)smF);

    prep_weffB4<<<H, 256>>>(dw, psi);
    {
        const int total = HW1B4_N + FW1B_F + FW3B_F + FW2B_F;
        prep_weights<<<(total + 255) / 256, 256>>>(hw1, fw1, fw3, fw2);
    }
    disco_head_mma<<<dim3(W / TW, H, B), TAD, smD>>>(x, db, hb1, hw2, hb2, out);
    ffn_fused<<<(unsigned)(M_PIX / 128), 512, smF>>>(out, fb1, fb2, fb3, out);
}

// round 17
// speedup vs baseline: 1.5546x; 1.5546x over previous
#include <cuda_runtime.h>

namespace {
constexpr int B = 2, H = 128, W = 256, MD = 34, LD = 32;
constexpr int NH = 4, SH = 64, K = 25, P = 7, R = 3;
constexpr int FF1 = 512, FF2 = 256;
constexpr int PP = P * P; // 49
constexpr long M_PIX = (long)B * H * W; // 65536

// ---------------- disco config (R15, measured best) ----------------
constexpr int TW   = 32;
constexpr int PIX  = 8;
constexpr int NGRP = TW / PIX;
constexpr int TAD  = 256;
constexpr int XCOLS = TW + 2 * R; // 38

constexpr int WEFFB4_N = 8 * 4 * 32;        // 1024 float4 per latitude
constexpr int HW1B4_N  = 4 * 4 * 4 * 32;    // 2048 float4
constexpr int FW1B4_N  = 64 * 3 * 32;       // 6144 float4 (paired, 5th in .xy)
constexpr int FW2B_F   = 16 * 32 * 4 * 32 * 2; // 131072 floats
constexpr int FW3B4_N  = 4 * 16 * 32;       // 2048 float4 (paired)

constexpr int OFF_SX   = 0;
constexpr int OFF_SXC  = OFF_SX + LD * P * XCOLS;
constexpr int OFF_SDB  = OFF_SXC + LD * TW;
constexpr int OFF_HB1  = OFF_SDB + SH;
constexpr int OFF_HW2  = OFF_HB1 + NH * 32;
constexpr int OFF_HB2  = OFF_HW2 + NH * 32;
constexpr int SMEM_D_F = OFF_HB2 + NH;     // 39.4 KB

__device__ __forceinline__ float gelu_exact(float v) {
    return 0.5f * v * (1.0f + erff(v * 0.70710678118654752440f));
}

__device__ __forceinline__ float f2tf_f(float f) {
    unsigned u;
    asm("cvt.rna.tf32.f32 %0, %1;" : "=r"(u) : "f"(f));
    return __uint_as_float(u);
}

__device__ __forceinline__ void mma_tf32(float c[4], const float4& a, const float2& b) {
    const unsigned* A = reinterpret_cast<const unsigned*>(&a);
    const unsigned* Bv = reinterpret_cast<const unsigned*>(&b);
    asm volatile(
        "mma.sync.aligned.m16n8k8.row.col.f32.tf32.tf32.f32 "
        "{%0,%1,%2,%3},{%4,%5,%6,%7},{%8,%9},{%0,%1,%2,%3};\n"
        : "+f"(c[0]), "+f"(c[1]), "+f"(c[2]), "+f"(c[3])
        : "r"(A[0]), "r"(A[1]), "r"(A[2]), "r"(A[3]), "r"(Bv[0]), "r"(Bv[1]));
}
} // namespace

// device-global scratch (no runtime allocation)
__device__ __align__(16) float4 g_weffB4[H * WEFFB4_N];
__device__ __align__(16) float4 g_hw1B4[HW1B4_N];
__device__ __align__(16) float4 g_fw1B4[FW1B4_N];
__device__ __align__(16) float  g_fw2B[FW2B_F];
__device__ __align__(16) float4 g_fw3B4[FW3B4_N];

// =====================================================================
// prep: fold psi into disco_w per latitude -> paired-k8 B-frags
// =====================================================================
__global__ void prep_weffB4(const float* __restrict__ dw,
                            const float* __restrict__ psi) {
    const int h = blockIdx.x;
    for (int e = threadIdx.x; e < WEFFB4_N; e += blockDim.x) {
        int lane = e & 31; int t = e >> 5;
        int kp = t & 3, nt = t >> 2;
        int g = lane >> 2, tg = lane & 3;
        int s = nt * 8 + g;
        int pj[4] = { 16 * kp + tg, 16 * kp + tg + 4,
                      16 * kp + 8 + tg, 16 * kp + 12 + tg };
        float v[4];
        #pragma unroll
        for (int j = 0; j < 4; j++) {
            float acc = 0.f;
            if (pj[j] < PP) {
                #pragma unroll
                for (int k = 0; k < K; k++)
                    acc += dw[s * K + k] * psi[(k * H + h) * PP + pj[j]];
            }
            v[j] = f2tf_f(acc);
        }
        g_weffB4[h * WEFFB4_N + e] = make_float4(v[0], v[1], v[2], v[3]);
    }
}

// =====================================================================
// prep: hw1 / fw1(paired) / fw3(paired) / fw2 — one kernel, range dispatch
// =====================================================================
__global__ void prep_weights(const float* __restrict__ hw1,
                             const float* __restrict__ fw1,
                             const float* __restrict__ fw3,
                             const float* __restrict__ fw2) {
    int e = blockIdx.x * blockDim.x + threadIdx.x;
    if (e < HW1B4_N) {
        int lane = e & 31; int t = e >> 5;
        int kp = t & 3; t >>= 2;
        int nt2 = t & 3; int n = t >> 2;
        int g = lane >> 2, tg = lane & 3;
        int o = nt2 * 8 + g;
        int s0 = 16 * kp + tg;
        g_hw1B4[e] = make_float4(
            f2tf_f(hw1[(n * SH + s0)      * 32 + o]),
            f2tf_f(hw1[(n * SH + s0 + 4)  * 32 + o]),
            f2tf_f(hw1[(n * SH + s0 + 8)  * 32 + o]),
            f2tf_f(hw1[(n * SH + s0 + 12) * 32 + o]));
        return;
    }
    e -= HW1B4_N;
    if (e < FW1B4_N) {
        // paired fw1: q = (nt*3+kp)*32+lane; kp<2 -> frags {2kp,2kp+1};
        // kp==2 -> frag 4 in .xy, zeros in .zw. frag(ks) = {k=8ks+tg, k=8ks+tg+4}
        int lane = e & 31; int t = e >> 5;
        int kp = t % 3, nt = t / 3;
        int g = lane >> 2, tg = lane & 3;
        int n = nt * 8 + g;
        auto f1 = [&](int k) -> float {
            return (k < MD) ? f2tf_f(fw1[k * FF1 + n]) : 0.f;
        };
        float4 o;
        if (kp < 2) {
            int ka = 2 * kp, kb = 2 * kp + 1;
            o = make_float4(f1(ka * 8 + tg), f1(ka * 8 + tg + 4),
                            f1(kb * 8 + tg), f1(kb * 8 + tg + 4));
        } else {
            o = make_float4(f1(32 + tg), f1(32 + tg + 4), 0.f, 0.f);
        }
        g_fw1B4[e] = o;
        return;
    }
    e -= FW1B4_N;
    if (e < FW3B4_N) {
        // paired fw3: q = (nt*16+kp)*32+lane; frags {2kp, 2kp+1};
        // frag(ks) = {fw3[(8ks+tg)*LD+n], fw3[(8ks+tg+4)*LD+n]}
        int lane = e & 31; int t = e >> 5;
        int kp = t & 15, nt = t >> 4;
        int g = lane >> 2, tg = lane & 3;
        int n = nt * 8 + g;
        int ka = 2 * kp, kb = 2 * kp + 1;
        g_fw3B4[e] = make_float4(
            f2tf_f(fw3[(ka * 8 + tg)     * LD + n]),
            f2tf_f(fw3[(ka * 8 + tg + 4) * LD + n]),
            f2tf_f(fw3[(kb * 8 + tg)     * LD + n]),
            f2tf_f(fw3[(kb * 8 + tg + 4) * LD + n]));
        return;
    }
    e -= FW3B4_N;
    if (e < FW2B_F) {
        int kc = e >> 13, r = e & 8191;
        int half = r & 1; r >>= 1;
        int lane = r & 31; r >>= 5;
        int ks = r & 3; int nt = r >> 2;
        int g = lane >> 2, tg = lane & 3;
        int k = kc * 32 + ks * 8 + tg + 4 * half;
        int n = nt * 8 + g;
        g_fw2B[e] = f2tf_f(fw2[k * FF2 + n]);
    }
}

// =====================================================================
// disco conv + head MLP + residual — byte-for-byte R15 (measured best)
// =====================================================================
__global__ __launch_bounds__(TAD, 2) void disco_head_mma(
    const float* __restrict__ x,   const float* __restrict__ db,
    const float* __restrict__ hb1, const float* __restrict__ hw2,
    const float* __restrict__ hb2, float* __restrict__ out)
{
    extern __shared__ float sm[];
    float* sx   = sm + OFF_SX;
    float* sxc  = sm + OFF_SXC;
    float* sdb  = sm + OFF_SDB;
    float* shb1 = sm + OFF_HB1;
    float* shw2 = sm + OFF_HW2;
    float* shb2 = sm + OFF_HB2;

    const int tid = threadIdx.x;
    const int lane = tid & 31, mt = tid >> 5;
    const int g  = lane >> 2, tg = lane & 3;
    const int w0 = blockIdx.x * TW;
    const int h  = blockIdx.y;
    const int b  = blockIdx.z;

    if (tid < SH) sdb[tid] = db[tid];
    if (tid < NH * 32) { shb1[tid] = hb1[tid]; shw2[tid] = hw2[tid]; }
    if (tid < NH) shb2[tid] = hb2[tid];

    for (int i = tid; i < LD * P * XCOLS; i += TAD) {
        int ld = i & 31; int pos = i >> 5;
        int r = pos / XCOLS, c = pos % XCOLS;
        int lat = h + r - R; lat = lat < 0 ? 0 : (lat > H - 1 ? H - 1 : lat);
        int lon = (w0 + c - R + W) & (W - 1);
        float v = x[((b * H + lat) * W + lon) * MD + ld];
        sx[(ld * P + r) * XCOLS + c] = f2tf_f(v);
        if (r == R && c >= R && c < R + TW) sxc[ld * TW + (c - R)] = v;
    }
    for (int i = tid; i < TW * 2; i += TAD) {
        int px = i >> 1, j = i & 1;
        int gi = ((b * H + h) * W + (w0 + px)) * MD + LD + j;
        out[gi] = x[gi];
    }
    __syncthreads();

    const int nh  = mt >> 1;
    const int ldA = nh * 8 + 4 * (mt & 1);
    const int px  = g;
    const int base0 = (ldA + 0) * P * XCOLS;
    const int base1 = (ldA + 1) * P * XCOLS;
    const int base2 = (ldA + 2) * P * XCOLS;
    const int base3 = (ldA + 3) * P * XCOLS;

    int roff0[8], roff1[8];
    #pragma unroll
    for (int ks = 0; ks < 8; ks++) {
        int p0 = ks * 8 + tg, p1 = p0 + 4;
        roff0[ks] = (p0 < PP) ? (p0 / 7) * XCOLS + (p0 % 7) : 0;
        roff1[ks] = (p1 < PP) ? (p1 / 7) * XCOLS + (p1 % 7) : 0;
    }

    const float4* swB4 = g_weffB4 + (long)h * WEFFB4_N;
    const float4* h1B4 = g_hw1B4;

    const int src0 = (lane & ~3) | (tg >> 1);
    const int src1 = src0 + 2;
    const bool odd = (tg & 1);

    for (int grp = 0; grp < NGRP; grp++) {
        const int cbase = grp * PIX + px;
        const int cb0 = base0 + cbase, cb1 = base1 + cbase;
        const int cb2 = base2 + cbase, cb3 = base3 + cbase;

        float c1[2][8][4] = {};
        #pragma unroll
        for (int kp = 0; kp < 4; kp++) {
            const int ka = 2 * kp, kb = 2 * kp + 1;
            float4 aA0, aA1, aB0, aB1;
            aA0.x = sx[cb0 + roff0[ka]]; aA0.y = sx[cb1 + roff0[ka]];
            aA0.z = sx[cb0 + roff1[ka]]; aA0.w = sx[cb1 + roff1[ka]];
            aA1.x = sx[cb2 + roff0[ka]]; aA1.y = sx[cb3 + roff0[ka]];
            aA1.z = sx[cb2 + roff1[ka]]; aA1.w = sx[cb3 + roff1[ka]];
            aB0.x = sx[cb0 + roff0[kb]]; aB0.y = sx[cb1 + roff0[kb]];
            aB0.z = sx[cb0 + roff1[kb]]; aB0.w = sx[cb1 + roff1[kb]];
            aB1.x = sx[cb2 + roff0[kb]]; aB1.y = sx[cb3 + roff0[kb]];
            aB1.z = sx[cb2 + roff1[kb]]; aB1.w = sx[cb3 + roff1[kb]];
            #pragma unroll
            for (int nt = 0; nt < 8; nt++) {
                const float4 wb = __ldg(&swB4[(nt * 4 + kp) * 32 + lane]);
                const float2 blo = make_float2(wb.x, wb.y);
                const float2 bhi = make_float2(wb.z, wb.w);
                mma_tf32(c1[0][nt], aA0, blo);
                mma_tf32(c1[1][nt], aA1, blo);
                mma_tf32(c1[0][nt], aB0, bhi);
                mma_tf32(c1[1][nt], aB1, bhi);
            }
        }

        float c2[2][4][4] = {};
        #pragma unroll
        for (int kp = 0; kp < 4; kp++) {
            float4 af[2][2];
            #pragma unroll
            for (int half = 0; half < 2; half++) {
                const int ks = 2 * kp + half;
                const int scol = ks * 8 + 2 * tg;
                const float b0 = sdb[scol], b1 = sdb[scol + 1];
                #pragma unroll
                for (int t = 0; t < 2; t++) {
                    const float y0 = f2tf_f(c1[t][ks][0] + b0);
                    const float y1 = f2tf_f(c1[t][ks][1] + b1);
                    const float y2 = f2tf_f(c1[t][ks][2] + b0);
                    const float y3 = f2tf_f(c1[t][ks][3] + b1);
                    const float u0 = __shfl_sync(0xffffffffu, y0, src0);
                    const float u1 = __shfl_sync(0xffffffffu, y1, src0);
                    const float u2 = __shfl_sync(0xffffffffu, y2, src0);
                    const float u3 = __shfl_sync(0xffffffffu, y3, src0);
                    const float v0 = __shfl_sync(0xffffffffu, y0, src1);
                    const float v1 = __shfl_sync(0xffffffffu, y1, src1);
                    const float v2 = __shfl_sync(0xffffffffu, y2, src1);
                    const float v3 = __shfl_sync(0xffffffffu, y3, src1);
                    af[t][half].x = odd ? u1 : u0;
                    af[t][half].y = odd ? u3 : u2;
                    af[t][half].z = odd ? v1 : v0;
                    af[t][half].w = odd ? v3 : v2;
                }
            }
            #pragma unroll
            for (int nt2 = 0; nt2 < 4; nt2++) {
                const float4 wb = __ldg(&h1B4[((nh * 4 + nt2) * 4 + kp) * 32 + lane]);
                const float2 blo = make_float2(wb.x, wb.y);
                const float2 bhi = make_float2(wb.z, wb.w);
                mma_tf32(c2[0][nt2], af[0][0], blo);
                mma_tf32(c2[1][nt2], af[1][0], blo);
                mma_tf32(c2[0][nt2], af[0][1], bhi);
                mma_tf32(c2[1][nt2], af[1][1], bhi);
            }
        }

        #pragma unroll
        for (int t = 0; t < 2; t++) {
            float part0 = 0.f, part1 = 0.f;
            #pragma unroll
            for (int nt2 = 0; nt2 < 4; nt2++) {
                const int o0 = nt2 * 8 + 2 * tg, o1 = o0 + 1;
                const float w0v = shw2[nh * 32 + o0], w1v = shw2[nh * 32 + o1];
                const float bb0 = shb1[nh * 32 + o0], bb1 = shb1[nh * 32 + o1];
                part0 += gelu_exact(c2[t][nt2][0] + bb0) * w0v
                       + gelu_exact(c2[t][nt2][1] + bb1) * w1v;
                part1 += gelu_exact(c2[t][nt2][2] + bb0) * w0v
                       + gelu_exact(c2[t][nt2][3] + bb1) * w1v;
            }
            part0 += __shfl_xor_sync(0xffffffffu, part0, 1);
            part0 += __shfl_xor_sync(0xffffffffu, part0, 2);
            part1 += __shfl_xor_sync(0xffffffffu, part1, 1);
            part1 += __shfl_xor_sync(0xffffffffu, part1, 2);
            if (tg == 0) {
                const int ld0 = ldA + 2 * t, ld1 = ld0 + 1;
                const int pxg = grp * PIX + px;
                const float v0 = part0 + shb2[nh] + sxc[ld0 * TW + pxg];
                const float v1 = part1 + shb2[nh] + sxc[ld1 * TW + pxg];
                const long o = ((long)(b * H + h) * W + w0 + pxg) * MD;
                out[o + ld0] = v0;
                out[o + ld1] = v1;
            }
        }
    }
}

// =====================================================================
// FFN fully fused — R15/M=64 form + paired fw1/fw3 fragment loads.
// =====================================================================
namespace {
constexpr int FB_BUF  = 10240;                 // 2048 t1c + 8192 fw2
constexpr int FST2_F  = 4 * 32 * 32 * 4;       // 16384
constexpr int FSF3    = FST2_F;                // sf3 offset (8192 floats)
constexpr int FFB1    = 24576;                 // fb1 offset
constexpr int SFN_F   = FFB1 + FF1;            // 25088 floats = 98 KB
}
__global__ __launch_bounds__(512) void ffn_fused(
    const float* __restrict__ xin, const float* __restrict__ fb1,
    const float* __restrict__ fb2, const float* __restrict__ fb3,
    float* __restrict__ out)
{
    extern __shared__ float sm[];
    float* sfb1 = sm + FFB1;
    const int tid = threadIdx.x, lane = tid & 31, w = tid >> 5;
    const int mw = w >> 2, nw = w & 3;
    const int g = lane >> 2, tg = lane & 3;
    const long r0 = (long)blockIdx.x * 64;

    sfb1[tid] = fb1[tid];

    {
        const int r = tid >> 3, rr7 = r & 7, rhi = (r >> 3) & 1, mt = r >> 4;
        const int kb = (tid & 7) * 5;
        #pragma unroll
        for (int j = 0; j < 5; j++) {
            const int k = kb + j;
            const float v = (k < MD) ? f2tf_f(xin[(r0 + r) * MD + k]) : 0.f;
            sm[((mt * 5 + (k >> 3)) * 32 + rr7 * 4 + (k & 3)) * 4
               + rhi + (((k >> 2) & 1) << 1)] = v;
        }
    }
    __syncthreads();
    float4 xfrag[5];
    #pragma unroll
    for (int ks = 0; ks < 5; ks++)
        xfrag[ks] = reinterpret_cast<const float4*>(sm)[(mw * 5 + ks) * 32 + lane];
    __syncthreads();

    float c2[8][4] = {};
    const float4* fw2v4 = reinterpret_cast<const float4*>(g_fw2B);

    for (int kc = 0; kc < 16; kc++) {
        float* buf  = sm + (kc & 1) * FB_BUF;
        float* st1c = buf;
        float* sB   = buf + 2048;

        {
            float4* dst = reinterpret_cast<float4*>(sB);
            #pragma unroll
            for (int i = 0; i < 4; i++)
                dst[tid + i * 512] = fw2v4[kc * 2048 + tid + i * 512];
        }

        // t1 chunk via paired fw1 fragments (3 LDG.128 replace 5 LDG.64)
        float c1[4] = {};
        {
            const int qb = (kc * 4 + nw) * 3;
            const float4 wA = __ldg(&g_fw1B4[(qb + 0) * 32 + lane]);
            const float4 wB = __ldg(&g_fw1B4[(qb + 1) * 32 + lane]);
            const float4 wC = __ldg(&g_fw1B4[(qb + 2) * 32 + lane]);
            mma_tf32(c1, xfrag[0], make_float2(wA.x, wA.y));
            mma_tf32(c1, xfrag[1], make_float2(wA.z, wA.w));
            mma_tf32(c1, xfrag[2], make_float2(wB.x, wB.y));
            mma_tf32(c1, xfrag[3], make_float2(wB.z, wB.w));
            mma_tf32(c1, xfrag[4], make_float2(wC.x, wC.y));
        }
        {
            const int n = kc * 32 + nw * 8 + 2 * tg;
            const float b0 = sfb1[n], b1 = sfb1[n + 1];
            const int kk0 = 2 * tg, kk1 = kk0 + 1;
            const int i0 = mw * 512 + (nw * 32 + g * 4 + (kk0 & 3)) * 4 + ((kk0 >> 2) << 1);
            const int i1 = mw * 512 + (nw * 32 + g * 4 + (kk1 & 3)) * 4 + ((kk1 >> 2) << 1);
            *reinterpret_cast<float2*>(st1c + i0) =
                make_float2(f2tf_f(gelu_exact(c1[0] + b0)),
                            f2tf_f(gelu_exact(c1[2] + b0)));
            *reinterpret_cast<float2*>(st1c + i1) =
                make_float2(f2tf_f(gelu_exact(c1[1] + b1)),
                            f2tf_f(gelu_exact(c1[3] + b1)));
        }
        __syncthreads();

        #pragma unroll
        for (int ks = 0; ks < 4; ks++) {
            float4 a = reinterpret_cast<const float4*>(st1c)[(mw * 4 + ks) * 32 + lane];
            #pragma unroll
            for (int ni = 0; ni < 8; ni++) {
                float2 bb = reinterpret_cast<const float2*>(sB)[((nw * 8 + ni) * 4 + ks) * 32 + lane];
                mma_tf32(c2[ni], a, bb);
            }
        }
    }
    __syncthreads();

    // t2 -> smem A-frags; paired fw3 frags staged late behind it
    float* sT2 = sm;
    float4* sf3v4 = reinterpret_cast<float4*>(sm + FSF3);
    {
        float4* dst = sf3v4;
        #pragma unroll
        for (int i = 0; i < 4; i++) dst[tid + i * 512] = g_fw3B4[tid + i * 512];
    }
    float2* sT2v2 = reinterpret_cast<float2*>(sT2);
    #pragma unroll
    for (int ni = 0; ni < 8; ni++) {
        const int nt = nw * 8 + ni;
        const int n2 = nt * 8 + 2 * tg;
        const int kk0 = n2 & 7, kk1 = kk0 + 1;
        const int base = (mw * 32 + nt) * 32;
        const int rgA = ((kk0 >> 2) & 1) << 1;
        const int i0 = (base + g * 4 + (kk0 & 3)) * 4 + rgA;
        const int i1 = (base + g * 4 + (kk1 & 3)) * 4 + rgA;
        const float b0 = fb2[n2], b1 = fb2[n2 + 1];
        sT2v2[i0 >> 1] = make_float2(f2tf_f(gelu_exact(c2[ni][0] + b0)),
                                     f2tf_f(gelu_exact(c2[ni][2] + b0)));
        sT2v2[i1 >> 1] = make_float2(f2tf_f(gelu_exact(c2[ni][1] + b1)),
                                     f2tf_f(gelu_exact(c2[ni][3] + b1)));
    }
    __syncthreads();

    // stage 3 with paired fw3 fragments: 16 kp steps, 2 MMAs each
    float c3[4] = {};
    #pragma unroll
    for (int kp = 0; kp < 16; kp++) {
        float4 a0 = reinterpret_cast<const float4*>(sT2)[(mw * 32 + 2 * kp) * 32 + lane];
        float4 a1 = reinterpret_cast<const float4*>(sT2)[(mw * 32 + 2 * kp + 1) * 32 + lane];
        float4 wb = sf3v4[(nw * 16 + kp) * 32 + lane];
        mma_tf32(c3, a0, make_float2(wb.x, wb.y));
        mma_tf32(c3, a1, make_float2(wb.z, wb.w));
    }

    const int col = nw * 8 + 2 * tg;
    const long rlo = r0 + mw * 16 + g, rhi = rlo + 8;
    const float b0 = fb3[col], b1 = fb3[col + 1];
    out[rlo * MD + col]     += c3[0] + b0;
    out[rlo * MD + col + 1] += c3[1] + b1;
    out[rhi * MD + col]     += c3[2] + b0;
    out[rhi * MD + col + 1] += c3[3] + b1;
}

extern "C" void kernel_launch(void* const* d_in, const int* in_sizes, int n_in,
                              void* d_out, int out_size) {
    const float* x   = (const float*)d_in[0];
    const float* psi = (const float*)d_in[1];
    const float* dw  = (const float*)d_in[2];
    const float* db  = (const float*)d_in[3];
    const float* hw1 = (const float*)d_in[4];
    const float* hb1 = (const float*)d_in[5];
    const float* hw2 = (const float*)d_in[6];
    const float* hb2 = (const float*)d_in[7];
    const float* fw1 = (const float*)d_in[8];
    const float* fb1 = (const float*)d_in[9];
    const float* fw2 = (const float*)d_in[10];
    const float* fb2 = (const float*)d_in[11];
    const float* fw3 = (const float*)d_in[12];
    const float* fb3 = (const float*)d_in[13];
    float* out = (float*)d_out;

    const size_t smD = SMEM_D_F * sizeof(float);
    const size_t smF = SFN_F * sizeof(float);
    cudaFuncSetAttribute(disco_head_mma, cudaFuncAttributeMaxDynamicSharedMemorySize, (int)smD);
    cudaFuncSetAttribute(ffn_fused, cudaFuncAttributeMaxDynamicSharedMemorySize, (int)smF);

    prep_weffB4<<<H, 256>>>(dw, psi);
    {
        const int total = HW1B4_N + FW1B4_N + FW3B4_N + FW2B_F;
        prep_weights<<<(total + 255) / 256, 256>>>(hw1, fw1, fw3, fw2);
    }
    disco_head_mma<<<dim3(W / TW, H, B), TAD, smD>>>(x, db, hb1, hw2, hb2, out);
    ffn_fused<<<(unsigned)(M_PIX / 64), 512, smF>>>(out, fb1, fb2, fb3, out);
}